// round 6
// baseline (speedup 1.0000x reference)
#include <cuda_runtime.h>
#include <cuda_bf16.h>
#include <cstdint>

// ---------------- Problem constants ----------------
#define BATCH   2048
#define NCOLS   32
#define CATD    2000
#define HID     128
#define VTOT    64000

// ---------------- Device scratch (no allocs allowed) ----------------
__device__ __align__(16) __nv_bfloat16 g_Wb[VTOT * HID];      // 16 MB  bf16 W_dec
__device__ __align__(16) float         g_c[VTOT];             // 256 KB c[v]
__device__ __align__(16) __nv_bfloat16 g_delta[BATCH * HID];  // 512 KB bf16 (y - ybar)
__device__ __align__(16) float         g_WT[VTOT * HID];      // 32 MB  W_enc^T [v][h]

__device__ __forceinline__ uint32_t smem_to_u32(const void* p) {
    uint32_t a;
    asm("{ .reg .u64 t; cvta.to.shared.u64 t, %1; cvt.u32.u64 %0, t; }" : "=r"(a) : "l"(p));
    return a;
}

#define CP_ASYNC_CG16(dst_smem, src_gmem) \
    asm volatile("cp.async.cg.shared.global [%0], [%1], 16;" \
        :: "r"(dst_smem), "l"(src_gmem) : "memory")
#define CP_ASYNC_COMMIT() asm volatile("cp.async.commit_group;" ::: "memory")
#define CP_ASYNC_WAIT(n)  asm volatile("cp.async.wait_group %0;" :: "n"(n) : "memory")

__device__ __forceinline__ void stg_cs_v4(float* p, float x, float y, float z, float w) {
    asm volatile("st.global.cs.v4.f32 [%0], {%1,%2,%3,%4};"
                 :: "l"(p), "f"(x), "f"(y), "f"(z), "f"(w) : "memory");
}

// ---------------- Kernel 0a: transpose W_enc [HID,VTOT] -> g_WT [VTOT,HID] ----------------
__global__ void __launch_bounds__(256) transpose_kernel(const float* __restrict__ Wenc) {
    extern __shared__ float st[];              // [128 v][129]
    int v0 = blockIdx.x * 128;
    int t  = threadIdx.x;
    #pragma unroll
    for (int it = 0; it < 64; ++it) {
        int idx = it * 256 + t;
        int v = idx & 127;
        int h = idx >> 7;
        st[v * 129 + h] = Wenc[(size_t)h * VTOT + v0 + v];
    }
    __syncthreads();
    #pragma unroll
    for (int it = 0; it < 16; ++it) {
        int idx = it * 256 + t;
        int h4 = (idx & 31) * 4;
        int v  = idx >> 5;
        float4 o;
        o.x = st[v * 129 + h4 + 0];
        o.y = st[v * 129 + h4 + 1];
        o.z = st[v * 129 + h4 + 2];
        o.w = st[v * 129 + h4 + 3];
        *reinterpret_cast<float4*>(g_WT + (size_t)(v0 + v) * HID + h4) = o;
    }
}

// ---------------- Kernel 0b: prep — W_dec -> bf16, c[v] = ybar . W_dec[v] + b_dec[v] ----------------
__global__ void __launch_bounds__(256) prep_kernel(const float* __restrict__ Wdec,
                                                   const float* __restrict__ benc,
                                                   const float* __restrict__ bdec) {
    int gw   = (blockIdx.x * 256 + threadIdx.x) >> 5;
    int lane = threadIdx.x & 31;
    if (gw >= VTOT) return;

    float4 w = *reinterpret_cast<const float4*>(Wdec + (size_t)gw * HID + lane * 4);

    float b0 = benc[lane * 4 + 0], b1 = benc[lane * 4 + 1];
    float b2 = benc[lane * 4 + 2], b3 = benc[lane * 4 + 3];
    float dot = w.x / (1.0f + __expf(-b0)) + w.y / (1.0f + __expf(-b1))
              + w.z / (1.0f + __expf(-b2)) + w.w / (1.0f + __expf(-b3));

    __nv_bfloat162 p0 = __floats2bfloat162_rn(w.x, w.y);
    __nv_bfloat162 p1 = __floats2bfloat162_rn(w.z, w.w);
    uint2 pk;
    pk.x = *reinterpret_cast<uint32_t*>(&p0);
    pk.y = *reinterpret_cast<uint32_t*>(&p1);
    *reinterpret_cast<uint2*>(g_Wb + (size_t)gw * HID + lane * 4) = pk;

    #pragma unroll
    for (int o = 16; o > 0; o >>= 1) dot += __shfl_xor_sync(0xffffffffu, dot, o);
    if (lane == 0) g_c[gw] = dot + bdec[gw];
}

// ---------------- Kernel 2: encode ----------------
__global__ void __launch_bounds__(256) encode_kernel(const int* __restrict__ xcat,
                                                     const float* __restrict__ benc,
                                                     float* __restrict__ yout) {
    int wid  = threadIdx.x >> 5;
    int lane = threadIdx.x & 31;
    int b    = blockIdx.x * 8 + wid;

    int gidx = xcat[b * NCOLS + lane] + lane * CATD;

    float a0 = 0.f, a1 = 0.f, a2 = 0.f, a3 = 0.f;
    #pragma unroll
    for (int i = 0; i < NCOLS; ++i) {
        int gi = __shfl_sync(0xffffffffu, gidx, i);
        float4 w = *reinterpret_cast<const float4*>(g_WT + (size_t)gi * HID + lane * 4);
        a0 += w.x; a1 += w.y; a2 += w.z; a3 += w.w;
    }

    float4 be = *reinterpret_cast<const float4*>(benc + lane * 4);
    float y0 = 1.0f / (1.0f + __expf(-(a0 + be.x)));
    float y1 = 1.0f / (1.0f + __expf(-(a1 + be.y)));
    float y2 = 1.0f / (1.0f + __expf(-(a2 + be.z)));
    float y3 = 1.0f / (1.0f + __expf(-(a3 + be.w)));
    if (yout) {
        float4 yv = {y0, y1, y2, y3};
        *reinterpret_cast<float4*>(yout + (size_t)b * HID + lane * 4) = yv;
    }
    float d0 = y0 - 1.0f / (1.0f + __expf(-be.x));
    float d1 = y1 - 1.0f / (1.0f + __expf(-be.y));
    float d2 = y2 - 1.0f / (1.0f + __expf(-be.z));
    float d3 = y3 - 1.0f / (1.0f + __expf(-be.w));
    __nv_bfloat162 p0 = __floats2bfloat162_rn(d0, d1);
    __nv_bfloat162 p1 = __floats2bfloat162_rn(d2, d3);
    uint2 pk;
    pk.x = *reinterpret_cast<uint32_t*>(&p0);
    pk.y = *reinterpret_cast<uint32_t*>(&p1);
    *reinterpret_cast<uint2*>(g_delta + (size_t)b * HID + lane * 4) = pk;
}

// ---------------- Kernel 3: decode GEMM ----------------
// 512 threads = 16 warps as 4(M) x 4(N), warp tile 32x32.
// A tile (128x128) loaded once; A FRAGMENTS HOISTED TO REGISTERS for all 8 ksteps.
// B streamed through a 3-stage cp.async ring; B rows permuted for STG.128 epilogue.

#define TILE_M 128
#define TILE_N 128
#define NGRP   9
#define NBLKS  (VTOT / TILE_N)           // 500
#define SROWB  272
#define TILE_BYTES (128 * SROWB)         // 34816
#define SM_A_OFF 0
#define SM_B_OFF TILE_BYTES
#define NSTAGE 3
#define SM_TOTAL ((1 + NSTAGE) * TILE_BYTES)   // 139264

__device__ __forceinline__ void ldmatrix_x4(uint32_t (&r)[4], uint32_t addr) {
    asm volatile("ldmatrix.sync.aligned.m8n8.x4.shared.b16 {%0,%1,%2,%3}, [%4];"
                 : "=r"(r[0]), "=r"(r[1]), "=r"(r[2]), "=r"(r[3]) : "r"(addr));
}
__device__ __forceinline__ void mma_bf16(float (&d)[4], const uint32_t (&a)[4], const uint32_t* b) {
    asm volatile(
        "mma.sync.aligned.m16n8k16.row.col.f32.bf16.bf16.f32 "
        "{%0,%1,%2,%3}, {%4,%5,%6,%7}, {%8,%9}, {%0,%1,%2,%3};"
        : "+f"(d[0]), "+f"(d[1]), "+f"(d[2]), "+f"(d[3])
        : "r"(a[0]), "r"(a[1]), "r"(a[2]), "r"(a[3]), "r"(b[0]), "r"(b[1]));
}

// B rows permuted within each 16-row group: g -> slot so a thread's C-fragment
// pair covers 4 consecutive global columns (enables STG.128).
__device__ __forceinline__ void load_B_tile(uint32_t sdst, const char* src, int tid) {
    #pragma unroll
    for (int it = 0; it < 4; ++it) {
        int idx = it * 512 + tid;                 // 0..2047 chunks of 16B
        int row = idx >> 4;
        int ch  = (idx & 15) * 16;
        int gg  = row & 15;
        int q   = gg >> 2, r = gg & 3;
        int slot = (r < 2) ? (q * 2 + r) : (8 + q * 2 + (r & 1));
        int prow = (row & ~15) | slot;
        CP_ASYNC_CG16(sdst + prow * SROWB + ch, src + row * 256 + ch);
    }
}

__global__ void __launch_bounds__(512, 1) decode_gemm(float* __restrict__ zout) {
    extern __shared__ char smem[];
    uint32_t sbase = smem_to_u32(smem);
    int tid  = threadIdx.x;
    int wid  = tid >> 5;
    int lane = tid & 31;
    int mblk = blockIdx.x;   // 0..15
    int ygrp = blockIdx.y;   // 0..NGRP-1

    // ---- A tile (group 1) ----
    const char* Asrc = reinterpret_cast<const char*>(g_delta + (size_t)mblk * TILE_M * HID);
    #pragma unroll
    for (int it = 0; it < 4; ++it) {
        int idx = it * 512 + tid;
        int row = idx >> 4;
        int ch  = (idx & 15) * 16;
        CP_ASYNC_CG16(sbase + SM_A_OFF + row * SROWB + ch, Asrc + row * 256 + ch);
    }
    CP_ASYNC_COMMIT();

    // ---- B stage 0, stage 1 (groups 2, 3) ----
    load_B_tile(sbase + SM_B_OFF, reinterpret_cast<const char*>(g_Wb + (size_t)ygrp * TILE_N * HID), tid);
    CP_ASYNC_COMMIT();
    {
        int nb1 = ygrp + NGRP;
        if (nb1 < NBLKS)
            load_B_tile(sbase + SM_B_OFF + TILE_BYTES,
                        reinterpret_cast<const char*>(g_Wb + (size_t)nb1 * TILE_N * HID), tid);
        CP_ASYNC_COMMIT();
    }

    int wm = wid & 3;        // M group (32 rows)
    int wn = wid >> 2;       // N group (32 cols)
    int j  = lane & 3;
    int colLoc = wn * 32 + j * 4;

    uint32_t aBase = sbase + SM_A_OFF + (uint32_t)(wm * 32 + (lane & 15)) * SROWB + ((lane >> 4) << 4);
    uint32_t bOff  = (uint32_t)(wn * 32 + ((lane >> 4) << 3) + (lane & 7)) * SROWB
                   + (((lane >> 3) & 1) << 4);
    int rowBase = mblk * TILE_M + wm * 32 + (lane >> 2);

    // ---- hoist A fragments to registers (all 8 ksteps) ----
    CP_ASYNC_WAIT(2);
    __syncthreads();
    uint32_t af[8][2][4];
    #pragma unroll
    for (int ks = 0; ks < 8; ++ks) {
        #pragma unroll
        for (int mf = 0; mf < 2; ++mf)
            ldmatrix_x4(af[ks][mf], aBase + (uint32_t)mf * 16u * SROWB + (uint32_t)ks * 32u);
    }

    CP_ASYNC_WAIT(1);
    __syncthreads();

    int nb = ygrp;
    int stage = 0;
    while (true) {
        int nb2 = nb + 2 * NGRP;
        if (nb2 < NBLKS) {
            int s2 = stage + 2;
            if (s2 >= NSTAGE) s2 -= NSTAGE;
            load_B_tile(sbase + SM_B_OFF + s2 * TILE_BYTES,
                        reinterpret_cast<const char*>(g_Wb + (size_t)nb2 * TILE_N * HID), tid);
        }
        CP_ASYNC_COMMIT();

        const float* ctab = g_c + (size_t)nb * TILE_N;
        float4 cv0 = *reinterpret_cast<const float4*>(ctab + colLoc);
        float4 cv1 = *reinterpret_cast<const float4*>(ctab + colLoc + 16);

        float acc[2][4][4];
        #pragma unroll
        for (int i = 0; i < 2; ++i)
            #pragma unroll
            for (int jj = 0; jj < 4; ++jj)
                #pragma unroll
                for (int k = 0; k < 4; ++k) acc[i][jj][k] = 0.0f;

        uint32_t bBase = sbase + SM_B_OFF + (uint32_t)stage * TILE_BYTES + bOff;
        #pragma unroll
        for (int ks = 0; ks < 8; ++ks) {
            uint32_t b[2][4];
            #pragma unroll
            for (int p = 0; p < 2; ++p)
                ldmatrix_x4(b[p], bBase + (uint32_t)p * 16u * SROWB + (uint32_t)ks * 32u);
            #pragma unroll
            for (int mf = 0; mf < 2; ++mf)
                #pragma unroll
                for (int nf = 0; nf < 4; ++nf)
                    mma_bf16(acc[mf][nf], af[ks][mf], &b[nf >> 1][(nf & 1) * 2]);
        }

        // ---- STG.128 streaming epilogue ----
        size_t colG = (size_t)nb * TILE_N + colLoc;
        #pragma unroll
        for (int mf = 0; mf < 2; ++mf) {
            float* z0 = zout + (size_t)(rowBase + mf * 16) * VTOT + colG;
            float* z1 = z0 + 8 * VTOT;
            stg_cs_v4(z0,      acc[mf][0][0] + cv0.x, acc[mf][0][1] + cv0.y,
                               acc[mf][1][0] + cv0.z, acc[mf][1][1] + cv0.w);
            stg_cs_v4(z1,      acc[mf][0][2] + cv0.x, acc[mf][0][3] + cv0.y,
                               acc[mf][1][2] + cv0.z, acc[mf][1][3] + cv0.w);
            stg_cs_v4(z0 + 16, acc[mf][2][0] + cv1.x, acc[mf][2][1] + cv1.y,
                               acc[mf][3][0] + cv1.z, acc[mf][3][1] + cv1.w);
            stg_cs_v4(z1 + 16, acc[mf][2][2] + cv1.x, acc[mf][2][3] + cv1.y,
                               acc[mf][3][2] + cv1.z, acc[mf][3][3] + cv1.w);
        }

        if (nb + NGRP >= NBLKS) break;
        CP_ASYNC_WAIT(1);
        __syncthreads();
        nb += NGRP;
        ++stage;
        if (stage >= NSTAGE) stage = 0;
    }
}

// ---------------- Launch ----------------
extern "C" void kernel_launch(void* const* d_in, const int* in_sizes, int n_in,
                              void* d_out, int out_size) {
    const int*   xcat = (const int*)d_in[0];
    const float* Wenc = (const float*)d_in[1];
    const float* benc = (const float*)d_in[2];
    const float* Wdec = (const float*)d_in[3];
    const float* bdec = (const float*)d_in[4];

    float* out = (float*)d_out;
    long long ztotal = (long long)BATCH * VTOT;
    long long zoff   = (long long)out_size - ztotal;
    if (zoff < 0) zoff = 0;
    float* zout = out + zoff;
    float* yout = (zoff >= (long long)BATCH * HID) ? out : nullptr;

    cudaFuncSetAttribute(decode_gemm, cudaFuncAttributeMaxDynamicSharedMemorySize, SM_TOTAL);
    cudaFuncSetAttribute(transpose_kernel, cudaFuncAttributeMaxDynamicSharedMemorySize, 128 * 129 * 4);

    transpose_kernel<<<VTOT / 128, 256, 128 * 129 * 4>>>(Wenc);
    prep_kernel<<<VTOT / 8, 256>>>(Wdec, benc, bdec);
    encode_kernel<<<BATCH / 8, 256>>>(xcat, benc, yout);
    decode_gemm<<<dim3(BATCH / TILE_M, NGRP), 512, SM_TOTAL>>>(zout);
}

// round 7
// speedup vs baseline: 1.0785x; 1.0785x over previous
#include <cuda_runtime.h>
#include <cuda_bf16.h>
#include <cstdint>

// ---------------- Problem constants ----------------
#define BATCH   2048
#define NCOLS   32
#define CATD    2000
#define HID     128
#define VTOT    64000

// ---------------- Device scratch (no allocs allowed) ----------------
__device__ __align__(16) __nv_bfloat16 g_Wb[VTOT * HID];      // 16 MB  bf16 W_dec
__device__ __align__(16) float         g_c[VTOT];             // 256 KB c[v]
__device__ __align__(16) __nv_bfloat16 g_delta[BATCH * HID];  // 512 KB bf16 (y - ybar)
__device__ __align__(16) float         g_WT[VTOT * HID];      // 32 MB  W_enc^T [v][h]

__device__ __forceinline__ uint32_t smem_to_u32(const void* p) {
    uint32_t a;
    asm("{ .reg .u64 t; cvta.to.shared.u64 t, %1; cvt.u32.u64 %0, t; }" : "=r"(a) : "l"(p));
    return a;
}

#define CP_ASYNC_CG16(dst_smem, src_gmem) \
    asm volatile("cp.async.cg.shared.global [%0], [%1], 16;" \
        :: "r"(dst_smem), "l"(src_gmem) : "memory")
#define CP_ASYNC_COMMIT() asm volatile("cp.async.commit_group;" ::: "memory")
#define CP_ASYNC_WAIT(n)  asm volatile("cp.async.wait_group %0;" :: "n"(n) : "memory")

__device__ __forceinline__ void stg_cs_v4(float* p, float x, float y, float z, float w) {
    asm volatile("st.global.cs.v4.f32 [%0], {%1,%2,%3,%4};"
                 :: "l"(p), "f"(x), "f"(y), "f"(z), "f"(w) : "memory");
}

// ---------------- Kernel 0a: transpose W_enc [HID,VTOT] -> g_WT [VTOT,HID] ----------------
__global__ void __launch_bounds__(256) transpose_kernel(const float* __restrict__ Wenc) {
    extern __shared__ float st[];              // [128 v][129]
    int v0 = blockIdx.x * 128;
    int t  = threadIdx.x;
    #pragma unroll
    for (int it = 0; it < 64; ++it) {
        int idx = it * 256 + t;
        int v = idx & 127;
        int h = idx >> 7;
        st[v * 129 + h] = Wenc[(size_t)h * VTOT + v0 + v];
    }
    __syncthreads();
    #pragma unroll
    for (int it = 0; it < 16; ++it) {
        int idx = it * 256 + t;
        int h4 = (idx & 31) * 4;
        int v  = idx >> 5;
        float4 o;
        o.x = st[v * 129 + h4 + 0];
        o.y = st[v * 129 + h4 + 1];
        o.z = st[v * 129 + h4 + 2];
        o.w = st[v * 129 + h4 + 3];
        *reinterpret_cast<float4*>(g_WT + (size_t)(v0 + v) * HID + h4) = o;
    }
}

// ---------------- Kernel 0b: prep ----------------
__global__ void __launch_bounds__(256) prep_kernel(const float* __restrict__ Wdec,
                                                   const float* __restrict__ benc,
                                                   const float* __restrict__ bdec) {
    int gw   = (blockIdx.x * 256 + threadIdx.x) >> 5;
    int lane = threadIdx.x & 31;
    if (gw >= VTOT) return;

    float4 w = *reinterpret_cast<const float4*>(Wdec + (size_t)gw * HID + lane * 4);

    float b0 = benc[lane * 4 + 0], b1 = benc[lane * 4 + 1];
    float b2 = benc[lane * 4 + 2], b3 = benc[lane * 4 + 3];
    float dot = w.x / (1.0f + __expf(-b0)) + w.y / (1.0f + __expf(-b1))
              + w.z / (1.0f + __expf(-b2)) + w.w / (1.0f + __expf(-b3));

    __nv_bfloat162 p0 = __floats2bfloat162_rn(w.x, w.y);
    __nv_bfloat162 p1 = __floats2bfloat162_rn(w.z, w.w);
    uint2 pk;
    pk.x = *reinterpret_cast<uint32_t*>(&p0);
    pk.y = *reinterpret_cast<uint32_t*>(&p1);
    *reinterpret_cast<uint2*>(g_Wb + (size_t)gw * HID + lane * 4) = pk;

    #pragma unroll
    for (int o = 16; o > 0; o >>= 1) dot += __shfl_xor_sync(0xffffffffu, dot, o);
    if (lane == 0) g_c[gw] = dot + bdec[gw];
}

// ---------------- Kernel 2: encode ----------------
__global__ void __launch_bounds__(256) encode_kernel(const int* __restrict__ xcat,
                                                     const float* __restrict__ benc,
                                                     float* __restrict__ yout) {
    int wid  = threadIdx.x >> 5;
    int lane = threadIdx.x & 31;
    int b    = blockIdx.x * 8 + wid;

    int gidx = xcat[b * NCOLS + lane] + lane * CATD;

    float a0 = 0.f, a1 = 0.f, a2 = 0.f, a3 = 0.f;
    #pragma unroll
    for (int i = 0; i < NCOLS; ++i) {
        int gi = __shfl_sync(0xffffffffu, gidx, i);
        float4 w = *reinterpret_cast<const float4*>(g_WT + (size_t)gi * HID + lane * 4);
        a0 += w.x; a1 += w.y; a2 += w.z; a3 += w.w;
    }

    float4 be = *reinterpret_cast<const float4*>(benc + lane * 4);
    float y0 = 1.0f / (1.0f + __expf(-(a0 + be.x)));
    float y1 = 1.0f / (1.0f + __expf(-(a1 + be.y)));
    float y2 = 1.0f / (1.0f + __expf(-(a2 + be.z)));
    float y3 = 1.0f / (1.0f + __expf(-(a3 + be.w)));
    if (yout) {
        float4 yv = {y0, y1, y2, y3};
        *reinterpret_cast<float4*>(yout + (size_t)b * HID + lane * 4) = yv;
    }
    float d0 = y0 - 1.0f / (1.0f + __expf(-be.x));
    float d1 = y1 - 1.0f / (1.0f + __expf(-be.y));
    float d2 = y2 - 1.0f / (1.0f + __expf(-be.z));
    float d3 = y3 - 1.0f / (1.0f + __expf(-be.w));
    __nv_bfloat162 p0 = __floats2bfloat162_rn(d0, d1);
    __nv_bfloat162 p1 = __floats2bfloat162_rn(d2, d3);
    uint2 pk;
    pk.x = *reinterpret_cast<uint32_t*>(&p0);
    pk.y = *reinterpret_cast<uint32_t*>(&p1);
    *reinterpret_cast<uint2*>(g_delta + (size_t)b * HID + lane * 4) = pk;
}

// ---------------- Kernel 3: decode GEMM (R5-validated config) ----------------
#define TILE_M 128
#define TILE_N 128
#define NGRP   18
#define NBLKS  (VTOT / TILE_N)           // 500
#define SROWB  272
#define TILE_BYTES (128 * SROWB)         // 34816
#define SM_A_OFF 0
#define SM_B_OFF TILE_BYTES
#define SM_TOTAL (3 * TILE_BYTES)        // 104448

__device__ __forceinline__ void ldmatrix_x4(uint32_t (&r)[4], uint32_t addr) {
    asm volatile("ldmatrix.sync.aligned.m8n8.x4.shared.b16 {%0,%1,%2,%3}, [%4];"
                 : "=r"(r[0]), "=r"(r[1]), "=r"(r[2]), "=r"(r[3]) : "r"(addr));
}
__device__ __forceinline__ void mma_bf16(float (&d)[4], const uint32_t (&a)[4], const uint32_t* b) {
    asm volatile(
        "mma.sync.aligned.m16n8k16.row.col.f32.bf16.bf16.f32 "
        "{%0,%1,%2,%3}, {%4,%5,%6,%7}, {%8,%9}, {%0,%1,%2,%3};"
        : "+f"(d[0]), "+f"(d[1]), "+f"(d[2]), "+f"(d[3])
        : "r"(a[0]), "r"(a[1]), "r"(a[2]), "r"(a[3]), "r"(b[0]), "r"(b[1]));
}

__device__ __forceinline__ void load_B_tile(uint32_t sdst, const char* src, int tid) {
    #pragma unroll
    for (int it = 0; it < 8; ++it) {
        int idx = it * 256 + tid;
        int row = idx >> 4;
        int ch  = (idx & 15) * 16;
        int gg  = row & 15;
        int q   = gg >> 2, r = gg & 3;
        int slot = (r < 2) ? (q * 2 + r) : (8 + q * 2 + (r & 1));
        int prow = (row & ~15) | slot;
        CP_ASYNC_CG16(sdst + prow * SROWB + ch, src + row * 256 + ch);
    }
}

__global__ void __launch_bounds__(256, 2) decode_gemm(float* __restrict__ zout) {
    extern __shared__ char smem[];
    uint32_t sbase = smem_to_u32(smem);
    int tid  = threadIdx.x;
    int wid  = tid >> 5;
    int lane = tid & 31;
    int mblk = blockIdx.x;
    int ygrp = blockIdx.y;

    const char* Asrc = reinterpret_cast<const char*>(g_delta + (size_t)mblk * TILE_M * HID);
    #pragma unroll
    for (int it = 0; it < 8; ++it) {
        int idx = it * 256 + tid;
        int row = idx >> 4;
        int ch  = (idx & 15) * 16;
        CP_ASYNC_CG16(sbase + SM_A_OFF + row * SROWB + ch, Asrc + row * 256 + ch);
    }
    int nb = ygrp;
    load_B_tile(sbase + SM_B_OFF, reinterpret_cast<const char*>(g_Wb + (size_t)nb * TILE_N * HID), tid);
    CP_ASYNC_COMMIT();

    int wm = wid & 1;
    int wn = wid >> 1;
    int j  = lane & 3;
    int colLoc = wn * 32 + j * 4;

    uint32_t aBase = sbase + SM_A_OFF + (uint32_t)(wm * 64 + (lane & 15)) * SROWB + ((lane >> 4) << 4);
    uint32_t bOff  = (uint32_t)(wn * 32 + ((lane >> 4) << 3) + (lane & 7)) * SROWB
                   + (((lane >> 3) & 1) << 4);
    int rowBase = mblk * TILE_M + wm * 64 + (lane >> 2);

    CP_ASYNC_WAIT(0);
    __syncthreads();

    int buf = 0;
    while (true) {
        int nbn = nb + NGRP;
        bool more = (nbn < NBLKS);
        if (more) {
            load_B_tile(sbase + SM_B_OFF + (buf ^ 1) * TILE_BYTES,
                        reinterpret_cast<const char*>(g_Wb + (size_t)nbn * TILE_N * HID), tid);
            CP_ASYNC_COMMIT();
        }

        const float* ctab = g_c + (size_t)nb * TILE_N;
        float4 cv[2];
        cv[0] = *reinterpret_cast<const float4*>(ctab + colLoc);
        cv[1] = *reinterpret_cast<const float4*>(ctab + colLoc + 16);

        float acc[4][4][4];
        #pragma unroll
        for (int i = 0; i < 4; ++i)
            #pragma unroll
            for (int jj = 0; jj < 4; ++jj)
                #pragma unroll
                for (int k = 0; k < 4; ++k) acc[i][jj][k] = 0.0f;

        uint32_t bBase = sbase + SM_B_OFF + (uint32_t)buf * TILE_BYTES + bOff;
        #pragma unroll
        for (int ks = 0; ks < 8; ++ks) {
            uint32_t koff = (uint32_t)ks * 32u;
            uint32_t a[4][4];
            uint32_t b[2][4];
            #pragma unroll
            for (int mf = 0; mf < 4; ++mf)
                ldmatrix_x4(a[mf], aBase + (uint32_t)mf * 16u * SROWB + koff);
            #pragma unroll
            for (int p = 0; p < 2; ++p)
                ldmatrix_x4(b[p], bBase + (uint32_t)p * 16u * SROWB + koff);
            #pragma unroll
            for (int mf = 0; mf < 4; ++mf)
                #pragma unroll
                for (int nf = 0; nf < 4; ++nf)
                    mma_bf16(acc[mf][nf], a[mf], &b[nf >> 1][(nf & 1) * 2]);
        }

        size_t colG = (size_t)nb * TILE_N + colLoc;
        #pragma unroll
        for (int mf = 0; mf < 4; ++mf) {
            float* z0 = zout + (size_t)(rowBase + mf * 16) * VTOT + colG;
            float* z1 = z0 + 8 * VTOT;
            stg_cs_v4(z0,      acc[mf][0][0] + cv[0].x, acc[mf][0][1] + cv[0].y,
                               acc[mf][1][0] + cv[0].z, acc[mf][1][1] + cv[0].w);
            stg_cs_v4(z1,      acc[mf][0][2] + cv[0].x, acc[mf][0][3] + cv[0].y,
                               acc[mf][1][2] + cv[0].z, acc[mf][1][3] + cv[0].w);
            stg_cs_v4(z0 + 16, acc[mf][2][0] + cv[1].x, acc[mf][2][1] + cv[1].y,
                               acc[mf][3][0] + cv[1].z, acc[mf][3][1] + cv[1].w);
            stg_cs_v4(z1 + 16, acc[mf][2][2] + cv[1].x, acc[mf][2][3] + cv[1].y,
                               acc[mf][3][2] + cv[1].z, acc[mf][3][3] + cv[1].w);
        }

        if (!more) break;
        CP_ASYNC_WAIT(0);
        __syncthreads();
        buf ^= 1;
        nb = nbn;
    }
}

// ---------------- Launch ----------------
extern "C" void kernel_launch(void* const* d_in, const int* in_sizes, int n_in,
                              void* d_out, int out_size) {
    const int*   xcat = (const int*)d_in[0];
    const float* Wenc = (const float*)d_in[1];
    const float* benc = (const float*)d_in[2];
    const float* Wdec = (const float*)d_in[3];
    const float* bdec = (const float*)d_in[4];

    float* out = (float*)d_out;
    long long ztotal = (long long)BATCH * VTOT;
    long long zoff   = (long long)out_size - ztotal;
    if (zoff < 0) zoff = 0;
    float* zout = out + zoff;
    float* yout = (zoff >= (long long)BATCH * HID) ? out : nullptr;

    cudaFuncSetAttribute(decode_gemm, cudaFuncAttributeMaxDynamicSharedMemorySize, SM_TOTAL);
    cudaFuncSetAttribute(transpose_kernel, cudaFuncAttributeMaxDynamicSharedMemorySize, 128 * 129 * 4);

    transpose_kernel<<<VTOT / 128, 256, 128 * 129 * 4>>>(Wenc);
    prep_kernel<<<VTOT / 8, 256>>>(Wdec, benc, bdec);
    encode_kernel<<<BATCH / 8, 256>>>(xcat, benc, yout);
    decode_gemm<<<dim3(BATCH / TILE_M, NGRP), 256, SM_TOTAL>>>(zout);
}